// round 8
// baseline (speedup 1.0000x reference)
#include <cuda_runtime.h>
#include <cuda_bf16.h>

// DCN-v1 cross network, algebraically collapsed, single kernel.
//   x_l = A_l*input + B_l;  A_{l+1} = A_l*(1+u_l) + t_l,
//   u_l = input.w_l (ORIGINAL input), t_l = sum_{k<l} b_k.w_l, B_L = sum b_k.
// Layout: thread tid owns float4 column #tid of ALL 8 rows of its CTA, so
// each W float4 is loaded ONCE per thread and reused for 8 rows (8x less L1
// traffic than warp-per-row; R7 ncu showed L1=73% / DRAM=29% -> L1-bound).
// Cross terms P[k][l] ride on the same loads as register FMAs.
// B=16384, D=1024, L=6. HBM floor = 128 MB ~= 16us @ 8TB/s.

#define CN_B 16384
#define CN_D 1024
#define CN_L 6
#define CN_R 8              // rows per CTA
#define CN_THREADS 256
#define CN_D4 (CN_D / 4)    // 256 float4 per row (== CN_THREADS)
#define CN_NU (CN_L * CN_R) // 48 u-values per CTA
#define CN_NP 15            // P pairs (k<l)
#define CN_NV (CN_NU + CN_NP)

__device__ __forceinline__ float dot4(const float4 a, const float4 b) {
    return fmaf(a.x, b.x, fmaf(a.y, b.y, fmaf(a.z, b.z, a.w * b.w)));
}

__global__ __launch_bounds__(CN_THREADS, 2)
void cross_network_kernel(const float* __restrict__ input,
                          const float* __restrict__ W,
                          const float* __restrict__ bias,
                          float* __restrict__ out)
{
    const int tid  = threadIdx.x;
    const int lane = tid & 31;
    const int warp = tid >> 5;

    // Warp partials: part[value][warp]. u[l][r] at l*8+r, P at 48+l(l-1)/2+k.
    __shared__ float part[CN_NV][8];
    __shared__ float sA[CN_R];

    const size_t row0 = (size_t)blockIdx.x * CN_R;
    const float4* in4 = reinterpret_cast<const float4*>(input);
    const float4* W4  = reinterpret_cast<const float4*>(W);
    const float4* b4  = reinterpret_cast<const float4*>(bias);

    // ---- 1) Input: thread owns float4 #tid of rows row0..row0+7 (MLP=8,
    //         coalesced per row; streaming hint keeps L1 for W/b). ----
    float4 xin[CN_R];
#pragma unroll
    for (int r = 0; r < CN_R; ++r)
        xin[r] = __ldcs(in4 + (row0 + r) * CN_D4 + tid);

    // ---- 2) Per layer: ONE W float4 -> 8 row partials + l cross terms. ----
#pragma unroll
    for (int l = 0; l < CN_L; ++l) {
        const float4 wv = __ldg(W4 + l * CN_D4 + tid);
        float v[CN_R + CN_L - 1];
#pragma unroll
        for (int r = 0; r < CN_R; ++r)
            v[r] = dot4(xin[r], wv);
#pragma unroll
        for (int k = 0; k < CN_L - 1; ++k) {
            if (k < l) {
                const float4 bv = __ldg(b4 + k * CN_D4 + tid);
                v[CN_R + k] = dot4(bv, wv);
            }
        }
        const int nv = CN_R + l;
        // Warp tree-reduce all nv values (independent chains).
#pragma unroll
        for (int o = 16; o > 0; o >>= 1) {
#pragma unroll
            for (int i = 0; i < CN_R + CN_L - 1; ++i)
                if (i < nv)
                    v[i] += __shfl_down_sync(0xffffffffu, v[i], o);
        }
        if (lane == 0) {
#pragma unroll
            for (int r = 0; r < CN_R; ++r)
                part[l * CN_R + r][warp] = v[r];
#pragma unroll
            for (int k = 0; k < CN_L - 1; ++k)
                if (k < l)
                    part[CN_NU + l * (l - 1) / 2 + k][warp] = v[CN_R + k];
        }
    }
    __syncthreads();

    // ---- 3) Warp 0, lanes 0..7: scalar recurrence per row. ----
    if (warp == 0 && lane < CN_R) {
        const int r = lane;
        float A = 1.f;
#pragma unroll
        for (int l = 0; l < CN_L; ++l) {
            float u = 0.f;
#pragma unroll
            for (int g = 0; g < 8; ++g) u += part[l * CN_R + r][g];
            float t = 0.f;
#pragma unroll
            for (int k = 0; k < l; ++k) {
                float pv = 0.f;
#pragma unroll
                for (int g = 0; g < 8; ++g)
                    pv += part[CN_NU + l * (l - 1) / 2 + k][g];
                t += pv;
            }
            A = fmaf(A, u, A) + t;   // A*(1+u) + t
        }
        sA[r] = A;
    }
    __syncthreads();

    // ---- 4) Epilogue: out = A[r]*input + sum_b (sum_b from L1-resident b). ----
    float4 sb = make_float4(0.f, 0.f, 0.f, 0.f);
#pragma unroll
    for (int k = 0; k < CN_L; ++k) {
        const float4 bv = __ldg(b4 + k * CN_D4 + tid);
        sb.x += bv.x; sb.y += bv.y; sb.z += bv.z; sb.w += bv.w;
    }
    float Ar[CN_R];
#pragma unroll
    for (int r = 0; r < CN_R; ++r) Ar[r] = sA[r];   // LDS broadcast

    float4* out4 = reinterpret_cast<float4*>(out);
#pragma unroll
    for (int r = 0; r < CN_R; ++r) {
        float4 o;
        o.x = fmaf(xin[r].x, Ar[r], sb.x);
        o.y = fmaf(xin[r].y, Ar[r], sb.y);
        o.z = fmaf(xin[r].z, Ar[r], sb.z);
        o.w = fmaf(xin[r].w, Ar[r], sb.w);
        __stcs(out4 + (row0 + r) * CN_D4 + tid, o);
    }
}

extern "C" void kernel_launch(void* const* d_in, const int* in_sizes, int n_in,
                              void* d_out, int out_size)
{
    const float* input = (const float*)d_in[0];
    const float* W     = (const float*)d_in[1];
    const float* b     = (const float*)d_in[2];
    float* out         = (float*)d_out;

    cross_network_kernel<<<CN_B / CN_R, CN_THREADS>>>(input, W, b, out);
}